// round 4
// baseline (speedup 1.0000x reference)
#include <cuda_runtime.h>
#include <cuda_bf16.h>

#define M 512
#define NBLK 1024          // 512 row-lines + 512 col-lines
#define MARGIN 0.2f

// per-CTA partials: x = mean (0 if invalid), y = valid flag (0/1)
__device__ float2 g_partials[NBLK];
__device__ int    g_count = 0;     // last-block ticket; reset by the finalizing block

__global__ __launch_bounds__(512, 4)
void side_kernel(const float* __restrict__ scores,
                 const int* __restrict__ labels,
                 float* __restrict__ out) {
    __shared__ __align__(16) float NV[M];   // compacted (neg + margin), padded w/ -1e30
    __shared__ __align__(16) float PV[M];   // compacted pos scores
    __shared__ int   warp_pos_cnt[16];
    __shared__ float warp_sums[16];
    __shared__ bool  is_last;

    const int b    = blockIdx.x;
    const int t    = threadIdx.x;
    const int lane = t & 31;
    const int w    = t >> 5;

    // row lines: contiguous; col lines: strided (L2-resident)
    int idx;
    if (b < M) idx = b * M + t;
    else       idx = t * M + (b - M);

    const float s   = scores[idx];
    const bool  pos = (labels[idx] == 1);

    // ---- compaction via ballot + warp-count scan ----
    const unsigned bal = __ballot_sync(0xffffffffu, pos);
    const unsigned lt  = (1u << lane) - 1u;
    if (lane == 0) warp_pos_cnt[w] = __popc(bal);
    __syncthreads();

    int base_pos = 0, np = 0;
    #pragma unroll
    for (int k = 0; k < 16; k++) {
        int c = warp_pos_cnt[k];
        np += c;
        if (k < w) base_pos += c;
    }
    const int nn     = M - np;
    const int nn_pad = (nn + 31) & ~31;      // <= M always

    if (pos) PV[base_pos + __popc(bal & lt)] = s;
    else     NV[(w * 32 - base_pos) + __popc(~bal & lt)] = s + MARGIN;
    // padding: max(-1e30, si) == si, and the padded count is subtracted below,
    // so pads contribute exactly zero.
    if (t < nn_pad - nn) NV[nn + t] = -1e30f;
    __syncthreads();

    // ---- pair loop: 4 threads per pos, each owns a quarter of NV ----
    const int   q      = t & 3;
    const int   pid    = t >> 2;
    const int   chunk  = nn_pad >> 2;        // multiple of 8
    const int   nit    = chunk >> 2;         // float4 iterations
    const float fchunk = (float)chunk;
    const float4* nv4  = reinterpret_cast<const float4*>(NV) + q * nit;

    float total = 0.f;
    for (int i = pid; i < np; i += 128) {
        const float si = PV[i];
        float a0 = 0.f, a1 = 0.f, a2 = 0.f, a3 = 0.f;
        #pragma unroll 8
        for (int k = 0; k < nit; k++) {
            float4 v = nv4[k];
            a0 += fmaxf(v.x, si);
            a1 += fmaxf(v.y, si);
            a2 += fmaxf(v.z, si);
            a3 += fmaxf(v.w, si);
        }
        // sum of relu over this chunk = sum(max) - chunk*si  (pads cancel)
        total = fmaf(-fchunk, si, total + ((a0 + a1) + (a2 + a3)));
    }

    // ---- deterministic CTA reduction ----
    #pragma unroll
    for (int o = 16; o > 0; o >>= 1)
        total += __shfl_down_sync(0xffffffffu, total, o);
    if (lane == 0) warp_sums[w] = total;
    __syncthreads();

    if (t < 32) {
        float v = (t < 16) ? warp_sums[t] : 0.f;
        #pragma unroll
        for (int o = 8; o > 0; o >>= 1)
            v += __shfl_down_sync(0xffffffffu, v, o);
        if (t == 0) {
            const bool  valid = (np > 0) && (nn > 0);
            const float cnt   = (float)np * (float)nn;   // exact in fp32
            float2 p;
            p.x = valid ? (v / cnt) : 0.f;
            p.y = valid ? 1.f : 0.f;
            g_partials[b] = p;
            __threadfence();
            int c = atomicAdd(&g_count, 1);
            is_last = (c == NBLK - 1);
        }
    }
    __syncthreads();

    // ---- last block: fixed-order global reduction + finalize ----
    if (is_last) {
        float m = 0.f, vv = 0.f;
        #pragma unroll
        for (int i = t; i < NBLK; i += 512) {
            float2 p = g_partials[i];
            m  += p.x;
            vv += p.y;
        }
        #pragma unroll
        for (int o = 16; o > 0; o >>= 1) {
            m  += __shfl_down_sync(0xffffffffu, m, o);
            vv += __shfl_down_sync(0xffffffffu, vv, o);
        }
        __shared__ float sm[16], sv[16];
        if (lane == 0) { sm[w] = m; sv[w] = vv; }
        __syncthreads();
        if (t < 32) {
            m  = (t < 16) ? sm[t] : 0.f;
            vv = (t < 16) ? sv[t] : 0.f;
            #pragma unroll
            for (int o = 8; o > 0; o >>= 1) {
                m  += __shfl_down_sync(0xffffffffu, m, o);
                vv += __shfl_down_sync(0xffffffffu, vv, o);
            }
            if (t == 0) {
                out[0] = m / vv;
                g_count = 0;                    // reset for next graph replay
            }
        }
    }
}

extern "C" void kernel_launch(void* const* d_in, const int* in_sizes, int n_in,
                              void* d_out, int out_size) {
    const float* scores = (const float*)d_in[0];
    const int*   labels = (const int*)d_in[1];
    float* out = (float*)d_out;

    side_kernel<<<NBLK, 512>>>(scores, labels, out);
}

// round 5
// speedup vs baseline: 2.3009x; 2.3009x over previous
#include <cuda_runtime.h>
#include <cuda_bf16.h>

#define M 512
#define NBLK 1024          // 512 row-lines + 512 col-lines
#define MARGIN 0.2f

__device__ float2 g_partials[NBLK];
__device__ int    g_count = 0;     // last-block ticket; reset by the finalizing block

__global__ __launch_bounds__(512, 4)
void side_kernel(const float* __restrict__ scores,
                 const int* __restrict__ labels,
                 float* __restrict__ out) {
    __shared__ __align__(16) float NV[M];   // compacted (neg + margin), padded w/ -1e30
    __shared__ __align__(16) float PV[M];   // compacted pos scores, zero-padded
    __shared__ int   warp_pos_cnt[16];
    __shared__ float warp_sums[16];
    __shared__ bool  is_last;

    const int b    = blockIdx.x;
    const int t    = threadIdx.x;
    const int lane = t & 31;
    const int w    = t >> 5;

    // row lines: contiguous; col lines: strided (L2-resident)
    int idx;
    if (b < M) idx = b * M + t;
    else       idx = t * M + (b - M);

    const float s   = scores[idx];
    const bool  pos = (labels[idx] == 1);

    // ---- compaction via ballot + warp-count scan ----
    const unsigned bal = __ballot_sync(0xffffffffu, pos);
    const unsigned lt  = (1u << lane) - 1u;
    if (lane == 0) warp_pos_cnt[w] = __popc(bal);
    __syncthreads();

    int base_pos = 0, np = 0;
    #pragma unroll
    for (int k = 0; k < 16; k++) {
        int c = warp_pos_cnt[k];
        np += c;
        if (k < w) base_pos += c;
    }
    const int nn     = M - np;
    const int nn_pad = (nn + 31) & ~31;      // <= M always

    if (pos) PV[base_pos + __popc(bal & lt)] = s;
    else     NV[(w * 32 - base_pos) + __popc(~bal & lt)] = s + MARGIN;
    // NV pads: max(-1e30, si) == si and padded count is subtracted -> exact zero.
    if (t < nn_pad - nn) NV[nn + t] = -1e30f;
    // PV pads: zero (contribution selected out below)
    if (t >= np) PV[t] = 0.f;
    __syncthreads();

    // ---- pair loop ----
    // Quarter of NV per *warp* (q = w&3): all 32 lanes read the SAME float4
    // -> pure broadcast, zero bank conflicts.
    // Each thread handles two pos entries per pass (i, i+128), stride 256.
    const int   q      = w & 3;
    const int   chunk  = nn_pad >> 2;        // multiple of 8
    const int   nit    = chunk >> 2;         // float4 iterations (multiple of 2)
    const float fchunk = (float)chunk;
    const float4* nv4  = reinterpret_cast<const float4*>(NV) + q * nit;

    float total = 0.f;
    // base in [0,128); i and i+128 both < 512 for all iterations (i <= 383)
    for (int i = lane + ((w >> 2) << 5); i < np; i += 256) {
        const float si0 = PV[i];
        const float si1 = PV[i + 128];       // in-bounds; zero-padded
        const bool  v1  = (i + 128) < np;

        float a0 = 0.f, a1 = 0.f, b0 = 0.f, b1 = 0.f;
        #pragma unroll 4
        for (int k = 0; k < nit; k++) {
            float4 v = nv4[k];               // broadcast LDS.128
            a0 += fmaxf(v.x, si0);
            a1 += fmaxf(v.y, si0);
            a0 += fmaxf(v.z, si0);
            a1 += fmaxf(v.w, si0);
            b0 += fmaxf(v.x, si1);
            b1 += fmaxf(v.y, si1);
            b0 += fmaxf(v.z, si1);
            b1 += fmaxf(v.w, si1);
        }
        total  = fmaf(-fchunk, si0, total + (a0 + a1));
        float c1 = fmaf(-fchunk, si1, b0 + b1);
        total += v1 ? c1 : 0.f;
    }

    // ---- deterministic CTA reduction ----
    #pragma unroll
    for (int o = 16; o > 0; o >>= 1)
        total += __shfl_down_sync(0xffffffffu, total, o);
    if (lane == 0) warp_sums[w] = total;
    __syncthreads();

    if (t < 32) {
        float v = (t < 16) ? warp_sums[t] : 0.f;
        #pragma unroll
        for (int o = 8; o > 0; o >>= 1)
            v += __shfl_down_sync(0xffffffffu, v, o);
        if (t == 0) {
            const bool  valid = (np > 0) && (nn > 0);
            const float cnt   = (float)np * (float)nn;   // exact in fp32
            float2 p;
            p.x = valid ? (v / cnt) : 0.f;
            p.y = valid ? 1.f : 0.f;
            g_partials[b] = p;
            __threadfence();
            int c = atomicAdd(&g_count, 1);
            is_last = (c == NBLK - 1);
        }
    }
    __syncthreads();

    // ---- last block: fixed-order global reduction + finalize ----
    if (is_last) {
        float m = 0.f, vv = 0.f;
        #pragma unroll
        for (int i = t; i < NBLK; i += 512) {
            float2 p = g_partials[i];
            m  += p.x;
            vv += p.y;
        }
        #pragma unroll
        for (int o = 16; o > 0; o >>= 1) {
            m  += __shfl_down_sync(0xffffffffu, m, o);
            vv += __shfl_down_sync(0xffffffffu, vv, o);
        }
        __shared__ float sm[16], sv[16];
        if (lane == 0) { sm[w] = m; sv[w] = vv; }
        __syncthreads();
        if (t < 32) {
            m  = (t < 16) ? sm[t] : 0.f;
            vv = (t < 16) ? sv[t] : 0.f;
            #pragma unroll
            for (int o = 8; o > 0; o >>= 1) {
                m  += __shfl_down_sync(0xffffffffu, m, o);
                vv += __shfl_down_sync(0xffffffffu, vv, o);
            }
            if (t == 0) {
                out[0] = m / vv;
                g_count = 0;                    // reset for next graph replay
            }
        }
    }
}

extern "C" void kernel_launch(void* const* d_in, const int* in_sizes, int n_in,
                              void* d_out, int out_size) {
    const float* scores = (const float*)d_in[0];
    const int*   labels = (const int*)d_in[1];
    float* out = (float*)d_out;

    side_kernel<<<NBLK, 512>>>(scores, labels, out);
}